// round 1
// baseline (speedup 1.0000x reference)
#include <cuda_runtime.h>
#include <math.h>

#define NB 8192
#define ND 256

// ---------------- scratch (no allocations allowed) ----------------
__device__ float  g_fT[ND * NB];      // normalized features, TRANSPOSED [d][i]  (8 MB)
__device__ float  g_dsq[NB];          // per-row squared distance to center
__device__ double g_sum_d, g_sumsq_d, g_center_d, g_margin_d, g_con_d;
__device__ int    g_cnt;

// ---------------- pass 0: zero accumulators (graph replays!) ----------------
__global__ void zero_kernel() {
    if (threadIdx.x == 0) {
        g_sum_d = 0.0; g_sumsq_d = 0.0; g_center_d = 0.0;
        g_margin_d = 0.0; g_con_d = 0.0; g_cnt = 0;
    }
}

// ---------------- pass 1: per-row stats + normalized transpose ----------------
// 1 warp per row; 8 warps per block.
__global__ void row_stats(const float* __restrict__ feat,
                          const int*   __restrict__ lab,
                          const float* __restrict__ cen) {
    int row  = blockIdx.x * 8 + (threadIdx.x >> 5);
    int lane = threadIdx.x & 31;
    const float4* fr = (const float4*)(feat + (size_t)row * ND);
    const float4* cr = (const float4*)cen;

    float dsq = 0.f, ssq = 0.f, sm = 0.f;
    float v[8];
#pragma unroll
    for (int c = 0; c < 2; c++) {
        int d4 = c * 32 + lane;              // float4 index 0..63
        float4 x = fr[d4], cv = cr[d4];
        v[c*4+0] = x.x; v[c*4+1] = x.y; v[c*4+2] = x.z; v[c*4+3] = x.w;
        float dx = x.x - cv.x, dy = x.y - cv.y, dz = x.z - cv.z, dw = x.w - cv.w;
        dsq += dx*dx + dy*dy + dz*dz + dw*dw;
        ssq += x.x*x.x + x.y*x.y + x.z*x.z + x.w*x.w;
        sm  += x.x + x.y + x.z + x.w;
    }
#pragma unroll
    for (int o = 16; o > 0; o >>= 1) {
        dsq += __shfl_xor_sync(0xffffffffu, dsq, o);
        ssq += __shfl_xor_sync(0xffffffffu, ssq, o);
        sm  += __shfl_xor_sync(0xffffffffu, sm , o);
    }
    float inv_norm = 1.f / fmaxf(sqrtf(ssq), 1e-12f);
#pragma unroll
    for (int c = 0; c < 2; c++) {
        int d0 = (c * 32 + lane) * 4;
#pragma unroll
        for (int e = 0; e < 4; e++)
            g_fT[(size_t)(d0 + e) * NB + row] = v[c*4+e] * inv_norm;
    }
    if (lane == 0) {
        g_dsq[row] = dsq;
        if (lab[row] == 0) {
            atomicAdd(&g_sum_d,    (double)sm);
            atomicAdd(&g_sumsq_d,  (double)ssq);
            atomicAdd(&g_center_d, (double)dsq);
            atomicAdd(&g_cnt, 1);
        }
    }
}

// ---------------- pass 2: sigma update + margin loss (1 block) ----------------
__global__ void sigma_margin(const int* __restrict__ lab,
                             const float* __restrict__ rsig) {
    __shared__ float  s_m;
    __shared__ double red[256];
    if (threadIdx.x == 0) {
        double n_el  = (double)g_cnt * (double)ND;
        double var   = (g_sumsq_d - g_sum_d * g_sum_d / n_el) / (n_el - 1.0);
        double sigma = 0.9 * (double)rsig[0] + 0.1 * sqrt(var);
        s_m = (float)(0.5 + 0.3 * sigma + 0.3 * (1.0 - 224.0 / 900.0));
    }
    __syncthreads();
    float m = s_m;
    double loc = 0.0;
    for (int i = threadIdx.x; i < NB; i += 256)
        if (lab[i] == 1) loc += (double)fmaxf(m - sqrtf(g_dsq[i]), 0.f);
    red[threadIdx.x] = loc;
    __syncthreads();
    for (int o = 128; o > 0; o >>= 1) {
        if (threadIdx.x < o) red[threadIdx.x] += red[threadIdx.x + o];
        __syncthreads();
    }
    if (threadIdx.x == 0) g_margin_d = red[0];
}

// ---------------- pass 3: contrastive (tiled fp32 sim + exp class-sums) ------
// 64x64 output tiles, k-major smem, 256 threads each computing a 4x4 microtile.
__global__ void contrastive(const int* __restrict__ lab) {
    extern __shared__ float smem[];
    float* As = smem;             // [256][64] k-major
    float* Bs = smem + 256 * 64;  // [256][64] k-major
    __shared__ int labS[64];

    const int tid = threadIdx.x;
    const int tx = tid & 15, ty = tid >> 4;
    const int i0 = blockIdx.x * 64;

    // load A tile (rows i0..i0+63, all 256 dims) — coalesced from transposed fT
    for (int f = tid; f < 4096; f += 256) {
        int k = f >> 4, c = (f & 15) << 2;
        *(float4*)&As[k * 64 + c] = *(const float4*)&g_fT[(size_t)k * NB + i0 + c];
    }

    float acc0[4] = {0.f,0.f,0.f,0.f};   // sum of exp over label-0 columns
    float acc1[4] = {0.f,0.f,0.f,0.f};   // sum of exp over label-1 columns
    const float invT = 1.0f / 0.07f;

    for (int j0 = 0; j0 < NB; j0 += 64) {
        __syncthreads();
        for (int f = tid; f < 4096; f += 256) {
            int k = f >> 4, c = (f & 15) << 2;
            *(float4*)&Bs[k * 64 + c] = *(const float4*)&g_fT[(size_t)k * NB + j0 + c];
        }
        if (tid < 64) labS[tid] = lab[j0 + tid];
        __syncthreads();

        float s[4][4];
#pragma unroll
        for (int m = 0; m < 4; m++)
#pragma unroll
            for (int n = 0; n < 4; n++) s[m][n] = 0.f;

#pragma unroll 4
        for (int k = 0; k < 256; k++) {
            float4 a = *(const float4*)&As[k * 64 + ty * 4];
            float4 b = *(const float4*)&Bs[k * 64 + tx * 4];
            float am[4] = {a.x, a.y, a.z, a.w};
            float bn[4] = {b.x, b.y, b.z, b.w};
#pragma unroll
            for (int m = 0; m < 4; m++)
#pragma unroll
                for (int n = 0; n < 4; n++) s[m][n] += am[m] * bn[n];
        }

        // epilogue: exp + class-masked accumulation, diagonal excluded exactly
#pragma unroll
        for (int n = 0; n < 4; n++) {
            int jg = j0 + tx * 4 + n;
            float w0 = (labS[tx * 4 + n] == 0) ? 1.f : 0.f;
            float w1 = 1.f - w0;
#pragma unroll
            for (int m = 0; m < 4; m++) {
                int ig = i0 + ty * 4 + m;
                float e = (ig == jg) ? 0.f : __expf(s[m][n] * invT);
                acc0[m] += e * w0;
                acc1[m] += e * w1;
            }
        }
    }

    // reduce across the 16 tx lanes (bits 0..3 of the lane id)
#pragma unroll
    for (int o = 8; o > 0; o >>= 1) {
#pragma unroll
        for (int m = 0; m < 4; m++) {
            acc0[m] += __shfl_xor_sync(0xffffffffu, acc0[m], o);
            acc1[m] += __shfl_xor_sync(0xffffffffu, acc1[m], o);
        }
    }

    if (tx == 0) {
        int n0 = g_cnt, n1 = NB - n0;
        double loc = 0.0;
#pragma unroll
        for (int m = 0; m < 4; m++) {
            int ig = i0 + ty * 4 + m;
            int li = lab[ig];
            float pos = (li == 0) ? acc0[m] : acc1[m];
            float neg = (li == 0) ? acc1[m] : acc0[m];
            int npos = ((li == 0) ? n0 : n1) - 1;
            int nneg = ((li == 0) ? n1 : n0);
            if (npos > 0 && nneg > 0)
                loc += (double)(logf(pos + neg + 1e-8f) - logf(pos));
        }
        atomicAdd(&g_con_d, loc);
    }
}

// ---------------- pass 4: combine ----------------
__global__ void finalize_k(float* out) {
    out[0] = (float)((1.0 * g_center_d + 1.0 * g_margin_d + 0.5 * g_con_d)
                     / (double)NB);
}

// ---------------- launch ----------------
extern "C" void kernel_launch(void* const* d_in, const int* in_sizes, int n_in,
                              void* d_out, int out_size) {
    const float* feat = (const float*)d_in[0];
    const int*   lab  = (const int*)d_in[1];
    const float* cen  = (const float*)d_in[2];
    const float* rsig = (const float*)d_in[3];
    float* out = (float*)d_out;

    cudaFuncSetAttribute(contrastive,
                         cudaFuncAttributeMaxDynamicSharedMemorySize, 131072);

    zero_kernel<<<1, 32>>>();
    row_stats<<<NB / 8, 256>>>(feat, lab, cen);
    sigma_margin<<<1, 256>>>(lab, rsig);
    contrastive<<<NB / 64, 256, 131072>>>(lab);
    finalize_k<<<1, 1>>>(out);
}

// round 3
// speedup vs baseline: 17.1427x; 17.1427x over previous
#include <cuda_runtime.h>
#include <cuda_bf16.h>
#include <math.h>
#include <stdint.h>

#define NB 8192
#define ND 256
#define BM 128
#define BN 128
#define BK 64

// exp(sim/T) = exp2(sim * (log2e / T))
#define CEXP 20.6099291551f

// ---------------- scratch (no allocations allowed) ----------------
__device__ __nv_bfloat16 g_fbf[NB * ND];   // normalized features, row-major bf16 (4 MB)
__device__ float  g_dsq[NB];
__device__ float  g_accL0[NB];             // per-row sum exp over label-0 cols (diag excl)
__device__ float  g_accT[NB];              // per-row sum exp over all cols (diag excl)
__device__ double g_sum_d, g_sumsq_d, g_center_d, g_margin_d, g_con_d;
__device__ int    g_cnt;

// ---------------- helpers ----------------
__device__ __forceinline__ uint32_t smem_u32(const void* p) {
    uint32_t a;
    asm("{ .reg .u64 t; cvta.to.shared.u64 t, %1; cvt.u32.u64 %0, t; }" : "=r"(a) : "l"(p));
    return a;
}
__device__ __forceinline__ float ex2f(float x) {
    float y; asm("ex2.approx.ftz.f32 %0, %1;" : "=f"(y) : "f"(x)); return y;
}
__device__ __forceinline__ void cp_async16(uint32_t s, const void* g) {
    asm volatile("cp.async.cg.shared.global [%0], [%1], 16;" :: "r"(s), "l"(g));
}
__device__ __forceinline__ void ldsm_x4(uint32_t* r, uint32_t addr) {
    asm volatile("ldmatrix.sync.aligned.m8n8.x4.shared.b16 {%0,%1,%2,%3}, [%4];"
                 : "=r"(r[0]), "=r"(r[1]), "=r"(r[2]), "=r"(r[3]) : "r"(addr));
}
__device__ __forceinline__ void mma16816(float* c, const uint32_t* a,
                                         uint32_t b0, uint32_t b1) {
    asm volatile("mma.sync.aligned.m16n8k16.row.col.f32.bf16.bf16.f32 "
                 "{%0,%1,%2,%3}, {%4,%5,%6,%7}, {%8,%9}, {%0,%1,%2,%3};"
                 : "+f"(c[0]), "+f"(c[1]), "+f"(c[2]), "+f"(c[3])
                 : "r"(a[0]), "r"(a[1]), "r"(a[2]), "r"(a[3]), "r"(b0), "r"(b1));
}

// ---------------- pass 0 ----------------
__global__ void zero_kernel() {
    if (threadIdx.x == 0) {
        g_sum_d = 0.0; g_sumsq_d = 0.0; g_center_d = 0.0;
        g_margin_d = 0.0; g_con_d = 0.0; g_cnt = 0;
    }
}

// ---------------- pass 1: stats + normalized bf16 features ----------------
__global__ void row_stats(const float* __restrict__ feat,
                          const int*   __restrict__ lab,
                          const float* __restrict__ cen) {
    int row  = blockIdx.x * 8 + (threadIdx.x >> 5);
    int lane = threadIdx.x & 31;
    const float4* fr = (const float4*)(feat + (size_t)row * ND);
    const float4* cr = (const float4*)cen;

    float dsq = 0.f, ssq = 0.f, sm = 0.f;
    float v[8];
#pragma unroll
    for (int c = 0; c < 2; c++) {
        int d4 = c * 32 + lane;
        float4 x = fr[d4], cv = cr[d4];
        v[c*4+0] = x.x; v[c*4+1] = x.y; v[c*4+2] = x.z; v[c*4+3] = x.w;
        float dx = x.x - cv.x, dy = x.y - cv.y, dz = x.z - cv.z, dw = x.w - cv.w;
        dsq += dx*dx + dy*dy + dz*dz + dw*dw;
        ssq += x.x*x.x + x.y*x.y + x.z*x.z + x.w*x.w;
        sm  += x.x + x.y + x.z + x.w;
    }
#pragma unroll
    for (int o = 16; o > 0; o >>= 1) {
        dsq += __shfl_xor_sync(0xffffffffu, dsq, o);
        ssq += __shfl_xor_sync(0xffffffffu, ssq, o);
        sm  += __shfl_xor_sync(0xffffffffu, sm , o);
    }
    float inv_norm = 1.f / fmaxf(sqrtf(ssq), 1e-12f);
#pragma unroll
    for (int c = 0; c < 2; c++) {
        int d0 = (c * 32 + lane) * 4;
        __nv_bfloat162 p0 = __floats2bfloat162_rn(v[c*4+0]*inv_norm, v[c*4+1]*inv_norm);
        __nv_bfloat162 p1 = __floats2bfloat162_rn(v[c*4+2]*inv_norm, v[c*4+3]*inv_norm);
        uint2 pk; pk.x = *(uint32_t*)&p0; pk.y = *(uint32_t*)&p1;
        *(uint2*)&g_fbf[(size_t)row * ND + d0] = pk;
    }
    if (lane == 0) {
        g_dsq[row] = dsq;
        g_accL0[row] = 0.f;
        g_accT[row]  = 0.f;
        if (lab[row] == 0) {
            atomicAdd(&g_sum_d,    (double)sm);
            atomicAdd(&g_sumsq_d,  (double)ssq);
            atomicAdd(&g_center_d, (double)dsq);
            atomicAdd(&g_cnt, 1);
        }
    }
}

// ---------------- pass 2: sigma + margin ----------------
__global__ void sigma_margin(const int* __restrict__ lab,
                             const float* __restrict__ rsig) {
    __shared__ float  s_m;
    __shared__ double red[256];
    if (threadIdx.x == 0) {
        double n_el  = (double)g_cnt * (double)ND;
        double var   = (g_sumsq_d - g_sum_d * g_sum_d / n_el) / (n_el - 1.0);
        double sigma = 0.9 * (double)rsig[0] + 0.1 * sqrt(var);
        s_m = (float)(0.5 + 0.3 * sigma + 0.3 * (1.0 - 224.0 / 900.0));
    }
    __syncthreads();
    float m = s_m;
    double loc = 0.0;
    for (int i = threadIdx.x; i < NB; i += 256)
        if (lab[i] == 1) loc += (double)fmaxf(m - sqrtf(g_dsq[i]), 0.f);
    red[threadIdx.x] = loc;
    __syncthreads();
    for (int o = 128; o > 0; o >>= 1) {
        if (threadIdx.x < o) red[threadIdx.x] += red[threadIdx.x + o];
        __syncthreads();
    }
    if (threadIdx.x == 0) g_margin_d = red[0];
}

// ---------------- pass 3: mma.sync bf16 contrastive ----------------
// 128x128 tile per block, 8 warps (4x2), warp tile 32x64, BK=64, 2-stage cp.async.
// smem per stage: A 16KB + B 16KB; stages at 0/32KB.
__global__ void __launch_bounds__(256, 2) contrast_mma(const int* __restrict__ lab) {
    extern __shared__ __align__(16) char dsm[];
    __shared__ float s_w0[BN];

    const uint32_t sbase = smem_u32(dsm);
    const int tid = threadIdx.x, lane = tid & 31, wid = tid >> 5;
    const int wm = wid & 3, wn = wid >> 2;
    const int i0 = blockIdx.x * BM, j0 = blockIdx.y * BN;

    for (int j = tid; j < BN; j += 256)
        s_w0[j] = (lab[j0 + j] == 0) ? 1.f : 0.f;

    float c[2][8][4];
#pragma unroll
    for (int fm = 0; fm < 2; fm++)
#pragma unroll
        for (int fn = 0; fn < 8; fn++)
#pragma unroll
            for (int e = 0; e < 4; e++) c[fm][fn][e] = 0.f;

    // ---- prefetch k-block kb into stage buf ----
    auto prefetch = [&](int kb, int buf) {
        uint32_t a_s = sbase + (uint32_t)buf * 32768u;
        uint32_t b_s = a_s + 16384u;
        const __nv_bfloat16* gA = g_fbf + (size_t)i0 * ND + kb * BK;
        const __nv_bfloat16* gB = g_fbf + (size_t)j0 * ND + kb * BK;
#pragma unroll
        for (int it = 0; it < 4; it++) {
            int ch = tid + it * 256;             // 1024 chunks of 16B
            int row = ch >> 3, c16 = ch & 7;
            uint32_t sw = (uint32_t)(row * 128 + ((c16 ^ (row & 7)) << 4));
            cp_async16(a_s + sw, gA + (size_t)row * ND + c16 * 8);
            cp_async16(b_s + sw, gB + (size_t)row * ND + c16 * 8);
        }
        asm volatile("cp.async.commit_group;" ::: "memory");
    };

    prefetch(0, 0);

#pragma unroll 1
    for (int kb = 0; kb < ND / BK; kb++) {
        if (kb + 1 < ND / BK) prefetch(kb + 1, (kb + 1) & 1);
        if (kb + 1 < ND / BK)
            asm volatile("cp.async.wait_group 1;" ::: "memory");
        else
            asm volatile("cp.async.wait_group 0;" ::: "memory");
        __syncthreads();

        uint32_t a_s = sbase + (uint32_t)(kb & 1) * 32768u;
        uint32_t b_s = a_s + 16384u;

#pragma unroll
        for (int ks = 0; ks < 4; ks++) {
            uint32_t a_frag[2][4], b_frag[4][4];
            int c16 = ks * 2 + (lane >> 4);
#pragma unroll
            for (int fm = 0; fm < 2; fm++) {
                int row = wm * 32 + fm * 16 + (lane & 15);
                ldsm_x4(a_frag[fm], a_s + row * 128 + ((c16 ^ (row & 7)) << 4));
            }
#pragma unroll
            for (int g = 0; g < 4; g++) {
                int row = wn * 64 + g * 16 + (lane & 15);
                ldsm_x4(b_frag[g], b_s + row * 128 + ((c16 ^ (row & 7)) << 4));
            }
#pragma unroll
            for (int fm = 0; fm < 2; fm++)
#pragma unroll
                for (int fn = 0; fn < 8; fn++) {
                    int g = fn >> 1;
                    uint32_t b0 = (fn & 1) ? b_frag[g][1] : b_frag[g][0];
                    uint32_t b1 = (fn & 1) ? b_frag[g][3] : b_frag[g][2];
                    mma16816(c[fm][fn], a_frag[fm], b0, b1);
                }
        }
        __syncthreads();
    }

    // ---- epilogue: exp + class sums, diagonal excluded exactly ----
    int r_base = i0 + wm * 32 + (lane >> 2);
#pragma unroll
    for (int fm = 0; fm < 2; fm++) {
        int r0 = r_base + fm * 16, r1 = r0 + 8;
        float s0_0 = 0.f, s0_T = 0.f, s1_0 = 0.f, s1_T = 0.f;
#pragma unroll
        for (int fn = 0; fn < 8; fn++) {
            int jl = wn * 64 + fn * 8 + (lane & 3) * 2;
            int jg = j0 + jl;
            float w0a = s_w0[jl], w0b = s_w0[jl + 1];
            float e;
            e = ex2f(c[fm][fn][0] * CEXP); if (r0 == jg)     e = 0.f;
            s0_0 = fmaf(e, w0a, s0_0); s0_T += e;
            e = ex2f(c[fm][fn][1] * CEXP); if (r0 == jg + 1) e = 0.f;
            s0_0 = fmaf(e, w0b, s0_0); s0_T += e;
            e = ex2f(c[fm][fn][2] * CEXP); if (r1 == jg)     e = 0.f;
            s1_0 = fmaf(e, w0a, s1_0); s1_T += e;
            e = ex2f(c[fm][fn][3] * CEXP); if (r1 == jg + 1) e = 0.f;
            s1_0 = fmaf(e, w0b, s1_0); s1_T += e;
        }
#pragma unroll
        for (int o = 1; o < 4; o <<= 1) {
            s0_0 += __shfl_xor_sync(0xffffffffu, s0_0, o);
            s0_T += __shfl_xor_sync(0xffffffffu, s0_T, o);
            s1_0 += __shfl_xor_sync(0xffffffffu, s1_0, o);
            s1_T += __shfl_xor_sync(0xffffffffu, s1_T, o);
        }
        if ((lane & 3) == 0) {
            atomicAdd(&g_accL0[r0], s0_0); atomicAdd(&g_accT[r0], s0_T);
            atomicAdd(&g_accL0[r1], s1_0); atomicAdd(&g_accT[r1], s1_T);
        }
    }
}

// ---------------- pass 4: per-row contrastive log + reduce ----------------
__global__ void con_final(const int* __restrict__ lab) {
    __shared__ double red[256];
    int i = blockIdx.x * 256 + threadIdx.x;
    int n0 = g_cnt, n1 = NB - n0;
    int li = lab[i];
    float aT = g_accT[i], a0 = g_accL0[i];
    float pos = (li == 0) ? a0 : (aT - a0);
    int npos = ((li == 0) ? n0 : n1) - 1;
    int nneg = (li == 0) ? n1 : n0;
    double loc = 0.0;
    if (npos > 0 && nneg > 0)
        loc = (double)(logf(aT + 1e-8f) - logf(pos));
    red[threadIdx.x] = loc;
    __syncthreads();
    for (int o = 128; o > 0; o >>= 1) {
        if (threadIdx.x < o) red[threadIdx.x] += red[threadIdx.x + o];
        __syncthreads();
    }
    if (threadIdx.x == 0) atomicAdd(&g_con_d, red[0]);
}

// ---------------- pass 5: combine ----------------
__global__ void finalize_k(float* out) {
    out[0] = (float)((1.0 * g_center_d + 1.0 * g_margin_d + 0.5 * g_con_d)
                     / (double)NB);
}

// ---------------- launch ----------------
extern "C" void kernel_launch(void* const* d_in, const int* in_sizes, int n_in,
                              void* d_out, int out_size) {
    const float* feat = (const float*)d_in[0];
    const int*   lab  = (const int*)d_in[1];
    const float* cen  = (const float*)d_in[2];
    const float* rsig = (const float*)d_in[3];
    float* out = (float*)d_out;

    cudaFuncSetAttribute(contrast_mma,
                         cudaFuncAttributeMaxDynamicSharedMemorySize, 65536);

    zero_kernel<<<1, 32>>>();
    row_stats<<<NB / 8, 256>>>(feat, lab, cen);
    sigma_margin<<<1, 256>>>(lab, rsig);
    dim3 grid(NB / BM, NB / BN);
    contrast_mma<<<grid, 256, 65536>>>(lab);
    con_final<<<NB / 256, 256>>>(lab);
    finalize_k<<<1, 1>>>(out);
}

// round 8
// speedup vs baseline: 18.0277x; 1.0516x over previous
#include <cuda_runtime.h>
#include <cuda_bf16.h>
#include <math.h>
#include <stdint.h>

#define NB 8192
#define ND 256
#define BM 128
#define BN 128
#define BK 64

// exp(sim/T) = exp2(sim * (log2e / T))
#define CEXP 20.6099291551f

// ---------------- scratch (no allocations allowed) ----------------
__device__ __nv_bfloat16 g_fbf[NB * ND];   // normalized features, row-major bf16 (4 MB)
__device__ float  g_dsq[NB];
__device__ float  g_accL0[NB];             // per-row sum exp over label-0 cols (diag excl)
__device__ float  g_accT[NB];              // per-row sum exp over all cols (diag excl)
__device__ float  g_m;                     // adaptive margin
__device__ double g_sum_d, g_sumsq_d, g_center_d, g_mc_d;
__device__ int    g_cnt;

// ---------------- helpers ----------------
__device__ __forceinline__ uint32_t smem_u32(const void* p) {
    uint32_t a;
    asm("{ .reg .u64 t; cvta.to.shared.u64 t, %1; cvt.u32.u64 %0, t; }" : "=r"(a) : "l"(p));
    return a;
}
__device__ __forceinline__ float ex2f(float x) {
    float y; asm("ex2.approx.ftz.f32 %0, %1;" : "=f"(y) : "f"(x)); return y;
}
__device__ __forceinline__ void cp_async16(uint32_t s, const void* g) {
    asm volatile("cp.async.cg.shared.global [%0], [%1], 16;" :: "r"(s), "l"(g));
}
__device__ __forceinline__ void ldsm_x4(uint32_t* r, uint32_t addr) {
    asm volatile("ldmatrix.sync.aligned.m8n8.x4.shared.b16 {%0,%1,%2,%3}, [%4];"
                 : "=r"(r[0]), "=r"(r[1]), "=r"(r[2]), "=r"(r[3]) : "r"(addr));
}
__device__ __forceinline__ void mma16816(float* c, const uint32_t* a,
                                         uint32_t b0, uint32_t b1) {
    asm volatile("mma.sync.aligned.m16n8k16.row.col.f32.bf16.bf16.f32 "
                 "{%0,%1,%2,%3}, {%4,%5,%6,%7}, {%8,%9}, {%0,%1,%2,%3};"
                 : "+f"(c[0]), "+f"(c[1]), "+f"(c[2]), "+f"(c[3])
                 : "r"(a[0]), "r"(a[1]), "r"(a[2]), "r"(a[3]), "r"(b0), "r"(b1));
}

// ---------------- pass 0 ----------------
__global__ void zero_kernel() {
    if (threadIdx.x == 0) {
        g_sum_d = 0.0; g_sumsq_d = 0.0; g_center_d = 0.0;
        g_mc_d = 0.0; g_cnt = 0;
    }
}

// ---------------- pass 1: stats + normalized bf16 features ----------------
__global__ void row_stats(const float* __restrict__ feat,
                          const int*   __restrict__ lab,
                          const float* __restrict__ cen) {
    int row  = blockIdx.x * 8 + (threadIdx.x >> 5);
    int lane = threadIdx.x & 31;
    const float4* fr = (const float4*)(feat + (size_t)row * ND);
    const float4* cr = (const float4*)cen;

    float dsq = 0.f, ssq = 0.f, sm = 0.f;
    float v[8];
#pragma unroll
    for (int c = 0; c < 2; c++) {
        int d4 = c * 32 + lane;
        float4 x = fr[d4], cv = cr[d4];
        v[c*4+0] = x.x; v[c*4+1] = x.y; v[c*4+2] = x.z; v[c*4+3] = x.w;
        float dx = x.x - cv.x, dy = x.y - cv.y, dz = x.z - cv.z, dw = x.w - cv.w;
        dsq += dx*dx + dy*dy + dz*dz + dw*dw;
        ssq += x.x*x.x + x.y*x.y + x.z*x.z + x.w*x.w;
        sm  += x.x + x.y + x.z + x.w;
    }
#pragma unroll
    for (int o = 16; o > 0; o >>= 1) {
        dsq += __shfl_xor_sync(0xffffffffu, dsq, o);
        ssq += __shfl_xor_sync(0xffffffffu, ssq, o);
        sm  += __shfl_xor_sync(0xffffffffu, sm , o);
    }
    float inv_norm = 1.f / fmaxf(sqrtf(ssq), 1e-12f);
#pragma unroll
    for (int c = 0; c < 2; c++) {
        int d0 = (c * 32 + lane) * 4;
        __nv_bfloat162 p0 = __floats2bfloat162_rn(v[c*4+0]*inv_norm, v[c*4+1]*inv_norm);
        __nv_bfloat162 p1 = __floats2bfloat162_rn(v[c*4+2]*inv_norm, v[c*4+3]*inv_norm);
        uint2 pk; pk.x = *(uint32_t*)&p0; pk.y = *(uint32_t*)&p1;
        *(uint2*)&g_fbf[(size_t)row * ND + d0] = pk;
    }
    if (lane == 0) {
        g_dsq[row] = dsq;
        g_accL0[row] = 0.f;
        g_accT[row]  = 0.f;
        if (lab[row] == 0) {
            atomicAdd(&g_sum_d,    (double)sm);
            atomicAdd(&g_sumsq_d,  (double)ssq);
            atomicAdd(&g_center_d, (double)dsq);
            atomicAdd(&g_cnt, 1);
        }
    }
}

// ---------------- pass 2: sigma scalar (1 thread) ----------------
__global__ void sigma_k(const float* __restrict__ rsig) {
    double n_el  = (double)g_cnt * (double)ND;
    double var   = (g_sumsq_d - g_sum_d * g_sum_d / n_el) / (n_el - 1.0);
    double sigma = 0.9 * (double)rsig[0] + 0.1 * sqrt(var);
    g_m = (float)(0.5 + 0.3 * sigma + 0.3 * (1.0 - 224.0 / 900.0));
}

// ---------------- pass 3: mma.sync bf16 contrastive, upper-tri tiles -------
// 128x128 tile, 8 warps (4x2), warp tile 32x64, BK=64, 2-stage cp.async.
// Only tiles tj>=ti computed; off-diag tiles accumulate BOTH row sums (query i)
// and column sums (query j, using e(i,j)=e(j,i)).
__global__ void __launch_bounds__(256, 2) contrast_mma(const int* __restrict__ lab) {
    if (blockIdx.y < blockIdx.x) return;    // lower triangle: skip
    extern __shared__ __align__(16) char dsm[];
    __shared__ float s_w0c[BN];             // label0 weight of columns j
    __shared__ float s_w0r[BM];             // label0 weight of rows i

    const uint32_t sbase = smem_u32(dsm);
    const int tid = threadIdx.x, lane = tid & 31, wid = tid >> 5;
    const int wm = wid & 3, wn = wid >> 2;
    const int i0 = blockIdx.x * BM, j0 = blockIdx.y * BN;
    const bool diag = (blockIdx.x == blockIdx.y);

    for (int j = tid; j < BN; j += 256)
        s_w0c[j] = (lab[j0 + j] == 0) ? 1.f : 0.f;
    for (int i = tid; i < BM; i += 256)
        s_w0r[i] = (lab[i0 + i] == 0) ? 1.f : 0.f;

    float c[2][8][4];
#pragma unroll
    for (int fm = 0; fm < 2; fm++)
#pragma unroll
        for (int fn = 0; fn < 8; fn++)
#pragma unroll
            for (int e = 0; e < 4; e++) c[fm][fn][e] = 0.f;

    auto prefetch = [&](int kb, int buf) {
        uint32_t a_s = sbase + (uint32_t)buf * 32768u;
        uint32_t b_s = a_s + 16384u;
        const __nv_bfloat16* gA = g_fbf + (size_t)i0 * ND + kb * BK;
        const __nv_bfloat16* gB = g_fbf + (size_t)j0 * ND + kb * BK;
#pragma unroll
        for (int it = 0; it < 4; it++) {
            int ch = tid + it * 256;
            int row = ch >> 3, c16 = ch & 7;
            uint32_t sw = (uint32_t)(row * 128 + ((c16 ^ (row & 7)) << 4));
            cp_async16(a_s + sw, gA + (size_t)row * ND + c16 * 8);
            cp_async16(b_s + sw, gB + (size_t)row * ND + c16 * 8);
        }
        asm volatile("cp.async.commit_group;" ::: "memory");
    };

    prefetch(0, 0);

#pragma unroll 1
    for (int kb = 0; kb < ND / BK; kb++) {
        if (kb + 1 < ND / BK) {
            prefetch(kb + 1, (kb + 1) & 1);
            asm volatile("cp.async.wait_group 1;" ::: "memory");
        } else {
            asm volatile("cp.async.wait_group 0;" ::: "memory");
        }
        __syncthreads();

        uint32_t a_s = sbase + (uint32_t)(kb & 1) * 32768u;
        uint32_t b_s = a_s + 16384u;

#pragma unroll
        for (int ks = 0; ks < 4; ks++) {
            uint32_t a_frag[2][4], b_frag[4][4];
            int c16 = ks * 2 + (lane >> 4);
#pragma unroll
            for (int fm = 0; fm < 2; fm++) {
                int row = wm * 32 + fm * 16 + (lane & 15);
                ldsm_x4(a_frag[fm], a_s + row * 128 + ((c16 ^ (row & 7)) << 4));
            }
#pragma unroll
            for (int g = 0; g < 4; g++) {
                int row = wn * 64 + g * 16 + (lane & 15);
                ldsm_x4(b_frag[g], b_s + row * 128 + ((c16 ^ (row & 7)) << 4));
            }
#pragma unroll
            for (int fm = 0; fm < 2; fm++)
#pragma unroll
                for (int fn = 0; fn < 8; fn++) {
                    int g = fn >> 1;
                    uint32_t b0 = (fn & 1) ? b_frag[g][1] : b_frag[g][0];
                    uint32_t b1 = (fn & 1) ? b_frag[g][3] : b_frag[g][2];
                    mma16816(c[fm][fn], a_frag[fm], b0, b1);
                }
        }
        __syncthreads();
    }

    // ---- epilogue: exp, row sums (query i) and col sums (query j) ----
    int r_base = i0 + wm * 32 + (lane >> 2);
    float colT[16], col0[16];
#pragma unroll
    for (int q = 0; q < 16; q++) { colT[q] = 0.f; col0[q] = 0.f; }

#pragma unroll
    for (int fm = 0; fm < 2; fm++) {
        int r0 = r_base + fm * 16, r1 = r0 + 8;
        float w0r0 = s_w0r[r0 - i0], w0r1 = s_w0r[r1 - i0];
        float s0_0 = 0.f, s0_T = 0.f, s1_0 = 0.f, s1_T = 0.f;
#pragma unroll
        for (int fn = 0; fn < 8; fn++) {
            int jl = wn * 64 + fn * 8 + (lane & 3) * 2;
            int jg = j0 + jl;
            float w0a = s_w0c[jl], w0b = s_w0c[jl + 1];
            float e00 = ex2f(c[fm][fn][0] * CEXP);
            float e01 = ex2f(c[fm][fn][1] * CEXP);
            float e10 = ex2f(c[fm][fn][2] * CEXP);
            float e11 = ex2f(c[fm][fn][3] * CEXP);
            if (diag) {
                if (r0 == jg)     e00 = 0.f;
                if (r0 == jg + 1) e01 = 0.f;
                if (r1 == jg)     e10 = 0.f;
                if (r1 == jg + 1) e11 = 0.f;
            }
            s0_0 = fmaf(e00, w0a, fmaf(e01, w0b, s0_0)); s0_T += e00 + e01;
            s1_0 = fmaf(e10, w0a, fmaf(e11, w0b, s1_0)); s1_T += e10 + e11;
            colT[fn*2]   += e00 + e10;
            colT[fn*2+1] += e01 + e11;
            col0[fn*2]   = fmaf(e00, w0r0, fmaf(e10, w0r1, col0[fn*2]));
            col0[fn*2+1] = fmaf(e01, w0r0, fmaf(e11, w0r1, col0[fn*2+1]));
        }
#pragma unroll
        for (int o = 1; o < 4; o <<= 1) {
            s0_0 += __shfl_xor_sync(0xffffffffu, s0_0, o);
            s0_T += __shfl_xor_sync(0xffffffffu, s0_T, o);
            s1_0 += __shfl_xor_sync(0xffffffffu, s1_0, o);
            s1_T += __shfl_xor_sync(0xffffffffu, s1_T, o);
        }
        if ((lane & 3) == 0) {
            atomicAdd(&g_accL0[r0], s0_0); atomicAdd(&g_accT[r0], s0_T);
            atomicAdd(&g_accL0[r1], s1_0); atomicAdd(&g_accT[r1], s1_T);
        }
    }

    if (!diag) {
        // reduce column partials across the 8 row-groups of the warp
#pragma unroll
        for (int q = 0; q < 16; q++) {
#pragma unroll
            for (int o = 4; o <= 16; o <<= 1) {
                colT[q] += __shfl_xor_sync(0xffffffffu, colT[q], o);
                col0[q] += __shfl_xor_sync(0xffffffffu, col0[q], o);
            }
        }
        if ((lane >> 2) == 0) {    // lanes 0..3 hold cols (lane&3)*2 per fn
#pragma unroll
            for (int fn = 0; fn < 8; fn++) {
                int jc = j0 + wn * 64 + fn * 8 + lane * 2;
                atomicAdd(&g_accT[jc],      colT[fn*2]);
                atomicAdd(&g_accT[jc + 1],  colT[fn*2+1]);
                atomicAdd(&g_accL0[jc],     col0[fn*2]);
                atomicAdd(&g_accL0[jc + 1], col0[fn*2+1]);
            }
        }
    }
}

// ---------------- pass 4: per-row margin + contrastive, reduce ----------------
__global__ void con_final(const int* __restrict__ lab) {
    __shared__ double red[256];
    int i = blockIdx.x * 256 + threadIdx.x;
    int n0 = g_cnt, n1 = NB - n0;
    int li = lab[i];
    float aT = g_accT[i], a0 = g_accL0[i];
    float pos = (li == 0) ? a0 : (aT - a0);
    int npos = ((li == 0) ? n0 : n1) - 1;
    int nneg = (li == 0) ? n1 : n0;
    double loc = 0.0;
    if (npos > 0 && nneg > 0)
        loc = 0.5 * (double)(logf(aT + 1e-8f) - logf(pos));   // GAMMA*r_con
    if (li == 1)
        loc += (double)fmaxf(g_m - sqrtf(g_dsq[i]), 0.f);     // BETA*r_margin
    red[threadIdx.x] = loc;
    __syncthreads();
    for (int o = 128; o > 0; o >>= 1) {
        if (threadIdx.x < o) red[threadIdx.x] += red[threadIdx.x + o];
        __syncthreads();
    }
    if (threadIdx.x == 0) atomicAdd(&g_mc_d, red[0]);
}

// ---------------- pass 5: combine ----------------
__global__ void finalize_k(float* out) {
    out[0] = (float)((g_center_d + g_mc_d) / (double)NB);
}

// ---------------- launch ----------------
extern "C" void kernel_launch(void* const* d_in, const int* in_sizes, int n_in,
                              void* d_out, int out_size) {
    const float* feat = (const float*)d_in[0];
    const int*   lab  = (const int*)d_in[1];
    const float* cen  = (const float*)d_in[2];
    const float* rsig = (const float*)d_in[3];
    float* out = (float*)d_out;

    cudaFuncSetAttribute(contrast_mma,
                         cudaFuncAttributeMaxDynamicSharedMemorySize, 65536);

    zero_kernel<<<1, 32>>>();
    row_stats<<<NB / 8, 256>>>(feat, lab, cen);
    sigma_k<<<1, 1>>>(rsig);
    dim3 grid(NB / BM, NB / BN);
    contrast_mma<<<grid, 256, 65536>>>(lab);
    con_final<<<NB / 256, 256>>>(lab);
    finalize_k<<<1, 1>>>(out);
}

// round 9
// speedup vs baseline: 27.7904x; 1.5415x over previous
#include <cuda_runtime.h>
#include <cuda_bf16.h>
#include <math.h>
#include <stdint.h>

#define NB 8192
#define ND 256
#define BM 128
#define BN 128
#define BK 64
#define NTILE 64            // NB/BM
#define NBLK 2080           // NTILE*(NTILE+1)/2

// exp(sim/T) = exp2(sim * (log2e / T))
#define CEXP 20.6099291551f

// ---------------- scratch (no allocations allowed) ----------------
__device__ __nv_bfloat16 g_fbf[NB * ND];
__device__ float  g_dsq[NB];
__device__ float  g_accL0[NB];
__device__ float  g_accT[NB];
__device__ double g_sum_d, g_sumsq_d, g_center_d, g_mc_d;
__device__ int    g_cnt;

// ---------------- helpers ----------------
__device__ __forceinline__ uint32_t smem_u32(const void* p) {
    uint32_t a;
    asm("{ .reg .u64 t; cvta.to.shared.u64 t, %1; cvt.u32.u64 %0, t; }" : "=r"(a) : "l"(p));
    return a;
}
__device__ __forceinline__ float ex2f(float x) {
    float y; asm("ex2.approx.ftz.f32 %0, %1;" : "=f"(y) : "f"(x)); return y;
}
__device__ __forceinline__ void cp_async16(uint32_t s, const void* g) {
    asm volatile("cp.async.cg.shared.global [%0], [%1], 16;" :: "r"(s), "l"(g));
}
__device__ __forceinline__ void ldsm_x4(uint32_t* r, uint32_t addr) {
    asm volatile("ldmatrix.sync.aligned.m8n8.x4.shared.b16 {%0,%1,%2,%3}, [%4];"
                 : "=r"(r[0]), "=r"(r[1]), "=r"(r[2]), "=r"(r[3]) : "r"(addr));
}
__device__ __forceinline__ void mma16816(float* c, const uint32_t* a,
                                         uint32_t b0, uint32_t b1) {
    asm volatile("mma.sync.aligned.m16n8k16.row.col.f32.bf16.bf16.f32 "
                 "{%0,%1,%2,%3}, {%4,%5,%6,%7}, {%8,%9}, {%0,%1,%2,%3};"
                 : "+f"(c[0]), "+f"(c[1]), "+f"(c[2]), "+f"(c[3])
                 : "r"(a[0]), "r"(a[1]), "r"(a[2]), "r"(a[3]), "r"(b0), "r"(b1));
}

// ---------------- pass 0 ----------------
__global__ void zero_kernel() {
    if (threadIdx.x == 0) {
        g_sum_d = 0.0; g_sumsq_d = 0.0; g_center_d = 0.0;
        g_mc_d = 0.0; g_cnt = 0;
    }
}

// ---------------- pass 1: stats + normalized bf16 features ----------------
__global__ void row_stats(const float* __restrict__ feat,
                          const int*   __restrict__ lab,
                          const float* __restrict__ cen) {
    int row  = blockIdx.x * 8 + (threadIdx.x >> 5);
    int lane = threadIdx.x & 31;
    const float4* fr = (const float4*)(feat + (size_t)row * ND);
    const float4* cr = (const float4*)cen;

    float dsq = 0.f, ssq = 0.f, sm = 0.f;
    float v[8];
#pragma unroll
    for (int c = 0; c < 2; c++) {
        int d4 = c * 32 + lane;
        float4 x = fr[d4], cv = cr[d4];
        v[c*4+0] = x.x; v[c*4+1] = x.y; v[c*4+2] = x.z; v[c*4+3] = x.w;
        float dx = x.x - cv.x, dy = x.y - cv.y, dz = x.z - cv.z, dw = x.w - cv.w;
        dsq += dx*dx + dy*dy + dz*dz + dw*dw;
        ssq += x.x*x.x + x.y*x.y + x.z*x.z + x.w*x.w;
        sm  += x.x + x.y + x.z + x.w;
    }
#pragma unroll
    for (int o = 16; o > 0; o >>= 1) {
        dsq += __shfl_xor_sync(0xffffffffu, dsq, o);
        ssq += __shfl_xor_sync(0xffffffffu, ssq, o);
        sm  += __shfl_xor_sync(0xffffffffu, sm , o);
    }
    float inv_norm = 1.f / fmaxf(sqrtf(ssq), 1e-12f);
#pragma unroll
    for (int c = 0; c < 2; c++) {
        int d0 = (c * 32 + lane) * 4;
        __nv_bfloat162 p0 = __floats2bfloat162_rn(v[c*4+0]*inv_norm, v[c*4+1]*inv_norm);
        __nv_bfloat162 p1 = __floats2bfloat162_rn(v[c*4+2]*inv_norm, v[c*4+3]*inv_norm);
        uint2 pk; pk.x = *(uint32_t*)&p0; pk.y = *(uint32_t*)&p1;
        *(uint2*)&g_fbf[(size_t)row * ND + d0] = pk;
    }
    if (lane == 0) {
        g_dsq[row] = dsq;
        g_accL0[row] = 0.f;
        g_accT[row]  = 0.f;
        if (lab[row] == 0) {
            atomicAdd(&g_sum_d,    (double)sm);
            atomicAdd(&g_sumsq_d,  (double)ssq);
            atomicAdd(&g_center_d, (double)dsq);
            atomicAdd(&g_cnt, 1);
        }
    }
}

// ---------------- pass 2: triangle-tiled bf16 mma contrastive ----------------
__global__ void __launch_bounds__(256, 2) contrast_mma(const int* __restrict__ lab) {
    extern __shared__ __align__(16) char dsm[];
    __shared__ float s_w0c[BN];
    __shared__ float s_w0r[BM];

    // invert linear triangle index -> (ti, tj), tj >= ti
    int b = blockIdx.x;
    int ti = (int)((129.0 - sqrt(129.0 * 129.0 - 8.0 * (double)b)) * 0.5);
    int base = ti * NTILE - (ti * (ti - 1)) / 2;
    if (b < base) { ti--; base = ti * NTILE - (ti * (ti - 1)) / 2; }
    else if (b >= base + (NTILE - ti)) { ti++; base = ti * NTILE - (ti * (ti - 1)) / 2; }
    const int tj = ti + (b - base);

    const uint32_t sbase = smem_u32(dsm);
    const int tid = threadIdx.x, lane = tid & 31, wid = tid >> 5;
    const int wm = wid & 3, wn = wid >> 2;
    const int i0 = ti * BM, j0 = tj * BN;
    const bool diag = (ti == tj);

    for (int j = tid; j < BN; j += 256)
        s_w0c[j] = (lab[j0 + j] == 0) ? 1.f : 0.f;
    for (int i = tid; i < BM; i += 256)
        s_w0r[i] = (lab[i0 + i] == 0) ? 1.f : 0.f;

    float c[2][8][4];
#pragma unroll
    for (int fm = 0; fm < 2; fm++)
#pragma unroll
        for (int fn = 0; fn < 8; fn++)
#pragma unroll
            for (int e = 0; e < 4; e++) c[fm][fn][e] = 0.f;

    auto prefetch = [&](int kb, int buf) {
        uint32_t a_s = sbase + (uint32_t)buf * 32768u;
        uint32_t b_s = a_s + 16384u;
        const __nv_bfloat16* gA = g_fbf + (size_t)i0 * ND + kb * BK;
        const __nv_bfloat16* gB = g_fbf + (size_t)j0 * ND + kb * BK;
#pragma unroll
        for (int it = 0; it < 4; it++) {
            int ch = tid + it * 256;
            int row = ch >> 3, c16 = ch & 7;
            uint32_t sw = (uint32_t)(row * 128 + ((c16 ^ (row & 7)) << 4));
            cp_async16(a_s + sw, gA + (size_t)row * ND + c16 * 8);
            cp_async16(b_s + sw, gB + (size_t)row * ND + c16 * 8);
        }
        asm volatile("cp.async.commit_group;" ::: "memory");
    };

    prefetch(0, 0);

#pragma unroll 1
    for (int kb = 0; kb < ND / BK; kb++) {
        if (kb + 1 < ND / BK) {
            prefetch(kb + 1, (kb + 1) & 1);
            asm volatile("cp.async.wait_group 1;" ::: "memory");
        } else {
            asm volatile("cp.async.wait_group 0;" ::: "memory");
        }
        __syncthreads();

        uint32_t a_s = sbase + (uint32_t)(kb & 1) * 32768u;
        uint32_t b_s = a_s + 16384u;

#pragma unroll
        for (int ks = 0; ks < 4; ks++) {
            uint32_t a_frag[2][4], b_frag[4][4];
            int c16 = ks * 2 + (lane >> 4);
#pragma unroll
            for (int fm = 0; fm < 2; fm++) {
                int row = wm * 32 + fm * 16 + (lane & 15);
                ldsm_x4(a_frag[fm], a_s + row * 128 + ((c16 ^ (row & 7)) << 4));
            }
#pragma unroll
            for (int g = 0; g < 4; g++) {
                int row = wn * 64 + g * 16 + (lane & 15);
                ldsm_x4(b_frag[g], b_s + row * 128 + ((c16 ^ (row & 7)) << 4));
            }
#pragma unroll
            for (int fm = 0; fm < 2; fm++)
#pragma unroll
                for (int fn = 0; fn < 8; fn++) {
                    int g = fn >> 1;
                    uint32_t b0 = (fn & 1) ? b_frag[g][1] : b_frag[g][0];
                    uint32_t b1 = (fn & 1) ? b_frag[g][3] : b_frag[g][2];
                    mma16816(c[fm][fn], a_frag[fm], b0, b1);
                }
        }
        __syncthreads();
    }

    // ---- epilogue (register-lean; fn outer, col partials short-lived) ----
    const int rl = wm * 32 + (lane >> 2);     // local row of fm=0/r0
    const int r_base = i0 + rl;
    float racc[8];                             // [fm*4 + {L0_r0, T_r0, L0_r1, T_r1}]
#pragma unroll
    for (int q = 0; q < 8; q++) racc[q] = 0.f;

    if (!diag) {
        float wr0 = s_w0r[rl], wr1 = s_w0r[rl + 8];
        float wr2 = s_w0r[rl + 16], wr3 = s_w0r[rl + 24];
#pragma unroll
        for (int fn = 0; fn < 8; fn++) {
            int jl = wn * 64 + fn * 8 + (lane & 3) * 2;
            float w0a = s_w0c[jl], w0b = s_w0c[jl + 1];
            float cTa = 0.f, cTb = 0.f, c0a = 0.f, c0b = 0.f;
#pragma unroll
            for (int fm = 0; fm < 2; fm++) {
                float e00 = ex2f(c[fm][fn][0] * CEXP);
                float e01 = ex2f(c[fm][fn][1] * CEXP);
                float e10 = ex2f(c[fm][fn][2] * CEXP);
                float e11 = ex2f(c[fm][fn][3] * CEXP);
                racc[fm*4+0] = fmaf(e00, w0a, fmaf(e01, w0b, racc[fm*4+0]));
                racc[fm*4+1] += e00 + e01;
                racc[fm*4+2] = fmaf(e10, w0a, fmaf(e11, w0b, racc[fm*4+2]));
                racc[fm*4+3] += e10 + e11;
                float wrA = fm ? wr2 : wr0, wrB = fm ? wr3 : wr1;
                cTa += e00 + e10; cTb += e01 + e11;
                c0a = fmaf(e00, wrA, fmaf(e10, wrB, c0a));
                c0b = fmaf(e01, wrA, fmaf(e11, wrB, c0b));
            }
#pragma unroll
            for (int o = 4; o <= 16; o <<= 1) {
                cTa += __shfl_xor_sync(0xffffffffu, cTa, o);
                cTb += __shfl_xor_sync(0xffffffffu, cTb, o);
                c0a += __shfl_xor_sync(0xffffffffu, c0a, o);
                c0b += __shfl_xor_sync(0xffffffffu, c0b, o);
            }
            if ((lane >> 2) == 0) {
                int jc = j0 + wn * 64 + fn * 8 + lane * 2;
                atomicAdd(&g_accT[jc],      cTa);
                atomicAdd(&g_accT[jc + 1],  cTb);
                atomicAdd(&g_accL0[jc],     c0a);
                atomicAdd(&g_accL0[jc + 1], c0b);
            }
        }
    } else {
#pragma unroll
        for (int fn = 0; fn < 8; fn++) {
            int jl = wn * 64 + fn * 8 + (lane & 3) * 2;
            int jg = j0 + jl;
            float w0a = s_w0c[jl], w0b = s_w0c[jl + 1];
#pragma unroll
            for (int fm = 0; fm < 2; fm++) {
                int r0 = r_base + fm * 16, r1 = r0 + 8;
                float e00 = ex2f(c[fm][fn][0] * CEXP);
                float e01 = ex2f(c[fm][fn][1] * CEXP);
                float e10 = ex2f(c[fm][fn][2] * CEXP);
                float e11 = ex2f(c[fm][fn][3] * CEXP);
                if (r0 == jg)     e00 = 0.f;
                if (r0 == jg + 1) e01 = 0.f;
                if (r1 == jg)     e10 = 0.f;
                if (r1 == jg + 1) e11 = 0.f;
                racc[fm*4+0] = fmaf(e00, w0a, fmaf(e01, w0b, racc[fm*4+0]));
                racc[fm*4+1] += e00 + e01;
                racc[fm*4+2] = fmaf(e10, w0a, fmaf(e11, w0b, racc[fm*4+2]));
                racc[fm*4+3] += e10 + e11;
            }
        }
    }

    // row reduction over the 4 column-lanes (offsets 1,2)
#pragma unroll
    for (int o = 1; o < 4; o <<= 1)
#pragma unroll
        for (int q = 0; q < 8; q++)
            racc[q] += __shfl_xor_sync(0xffffffffu, racc[q], o);

    if ((lane & 3) == 0) {
#pragma unroll
        for (int fm = 0; fm < 2; fm++) {
            int r0 = r_base + fm * 16, r1 = r0 + 8;
            atomicAdd(&g_accL0[r0], racc[fm*4+0]);
            atomicAdd(&g_accT[r0],  racc[fm*4+1]);
            atomicAdd(&g_accL0[r1], racc[fm*4+2]);
            atomicAdd(&g_accT[r1],  racc[fm*4+3]);
        }
    }
}

// ---------------- pass 3: per-row margin + contrastive, reduce ----------------
__global__ void con_final(const int* __restrict__ lab,
                          const float* __restrict__ rsig) {
    __shared__ double red[256];
    int i = blockIdx.x * 256 + threadIdx.x;
    int n0 = g_cnt, n1 = NB - n0;

    // adaptive margin recomputed per block (cheap scalar doubles)
    double n_el  = (double)n0 * (double)ND;
    double var   = (g_sumsq_d - g_sum_d * g_sum_d / n_el) / (n_el - 1.0);
    double sigma = 0.9 * (double)rsig[0] + 0.1 * sqrt(var);
    float m = (float)(0.5 + 0.3 * sigma + 0.3 * (1.0 - 224.0 / 900.0));

    int li = lab[i];
    float aT = g_accT[i], a0 = g_accL0[i];
    float pos = (li == 0) ? a0 : (aT - a0);
    int npos = ((li == 0) ? n0 : n1) - 1;
    int nneg = (li == 0) ? n1 : n0;
    double loc = 0.0;
    if (npos > 0 && nneg > 0)
        loc = 0.5 * (double)(logf(aT + 1e-8f) - logf(pos));   // GAMMA*r_con
    if (li == 1)
        loc += (double)fmaxf(m - sqrtf(g_dsq[i]), 0.f);       // BETA*r_margin
    red[threadIdx.x] = loc;
    __syncthreads();
    for (int o = 128; o > 0; o >>= 1) {
        if (threadIdx.x < o) red[threadIdx.x] += red[threadIdx.x + o];
        __syncthreads();
    }
    if (threadIdx.x == 0) atomicAdd(&g_mc_d, red[0]);
}

// ---------------- pass 4: combine ----------------
__global__ void finalize_k(float* out) {
    out[0] = (float)((g_center_d + g_mc_d) / (double)NB);
}

// ---------------- launch ----------------
extern "C" void kernel_launch(void* const* d_in, const int* in_sizes, int n_in,
                              void* d_out, int out_size) {
    const float* feat = (const float*)d_in[0];
    const int*   lab  = (const int*)d_in[1];
    const float* cen  = (const float*)d_in[2];
    const float* rsig = (const float*)d_in[3];
    float* out = (float*)d_out;

    cudaFuncSetAttribute(contrast_mma,
                         cudaFuncAttributeMaxDynamicSharedMemorySize, 65536);

    zero_kernel<<<1, 32>>>();
    row_stats<<<NB / 8, 256>>>(feat, lab, cen);
    contrast_mma<<<NBLK, 256, 65536>>>(lab);
    con_final<<<NB / 256, 256>>>(lab, rsig);
    finalize_k<<<1, 1>>>(out);
}

// round 10
// speedup vs baseline: 29.2435x; 1.0523x over previous
#include <cuda_runtime.h>
#include <cuda_bf16.h>
#include <math.h>
#include <stdint.h>

#define NB 8192
#define ND 256
#define BM 128
#define BN 128
#define BK 64
#define NTILE 64            // NB/BM
#define NBLK 2080           // NTILE*(NTILE+1)/2
#define RSB 1024            // row_stats blocks

// exp(sim/T) = exp2(sim * (log2e / T))
#define CEXP 20.6099291551f

// ---------------- scratch (no allocations allowed) ----------------
__device__ __nv_bfloat16 g_fbf[NB * ND];
__device__ float  g_dsq[NB];
__device__ float  g_accL0[NB];
__device__ float  g_accT[NB];
__device__ double p_sum[RSB], p_ssq[RSB], p_ctr[RSB];
__device__ int    p_cnt[RSB];
__device__ double g_center_d, g_mc_d;
__device__ float  g_m;
__device__ int    g_cnt;
__device__ unsigned g_ticket;

// ---------------- helpers ----------------
__device__ __forceinline__ uint32_t smem_u32(const void* p) {
    uint32_t a;
    asm("{ .reg .u64 t; cvta.to.shared.u64 t, %1; cvt.u32.u64 %0, t; }" : "=r"(a) : "l"(p));
    return a;
}
__device__ __forceinline__ float ex2f(float x) {
    float y; asm("ex2.approx.ftz.f32 %0, %1;" : "=f"(y) : "f"(x)); return y;
}
__device__ __forceinline__ void cp_async16(uint32_t s, const void* g) {
    asm volatile("cp.async.cg.shared.global [%0], [%1], 16;" :: "r"(s), "l"(g));
}
__device__ __forceinline__ void ldsm_x4(uint32_t* r, uint32_t addr) {
    asm volatile("ldmatrix.sync.aligned.m8n8.x4.shared.b16 {%0,%1,%2,%3}, [%4];"
                 : "=r"(r[0]), "=r"(r[1]), "=r"(r[2]), "=r"(r[3]) : "r"(addr));
}
__device__ __forceinline__ void mma16816(float* c, const uint32_t* a,
                                         uint32_t b0, uint32_t b1) {
    asm volatile("mma.sync.aligned.m16n8k16.row.col.f32.bf16.bf16.f32 "
                 "{%0,%1,%2,%3}, {%4,%5,%6,%7}, {%8,%9}, {%0,%1,%2,%3};"
                 : "+f"(c[0]), "+f"(c[1]), "+f"(c[2]), "+f"(c[3])
                 : "r"(a[0]), "r"(a[1]), "r"(a[2]), "r"(a[3]), "r"(b0), "r"(b1));
}

// ---------------- pass 1: stats + normalized bf16 features ----------------
// 8 rows/block, per-block partials (no pre-zeroed global atomics needed).
__global__ void row_stats(const float* __restrict__ feat,
                          const int*   __restrict__ lab,
                          const float* __restrict__ cen) {
    __shared__ double sh_sm[8], sh_ssq[8], sh_ctr[8];
    __shared__ int    sh_cnt[8];
    int wrp  = threadIdx.x >> 5;
    int row  = blockIdx.x * 8 + wrp;
    int lane = threadIdx.x & 31;
    const float4* fr = (const float4*)(feat + (size_t)row * ND);
    const float4* cr = (const float4*)cen;

    float dsq = 0.f, ssq = 0.f, sm = 0.f;
    float v[8];
#pragma unroll
    for (int c = 0; c < 2; c++) {
        int d4 = c * 32 + lane;
        float4 x = fr[d4], cv = cr[d4];
        v[c*4+0] = x.x; v[c*4+1] = x.y; v[c*4+2] = x.z; v[c*4+3] = x.w;
        float dx = x.x - cv.x, dy = x.y - cv.y, dz = x.z - cv.z, dw = x.w - cv.w;
        dsq += dx*dx + dy*dy + dz*dz + dw*dw;
        ssq += x.x*x.x + x.y*x.y + x.z*x.z + x.w*x.w;
        sm  += x.x + x.y + x.z + x.w;
    }
#pragma unroll
    for (int o = 16; o > 0; o >>= 1) {
        dsq += __shfl_xor_sync(0xffffffffu, dsq, o);
        ssq += __shfl_xor_sync(0xffffffffu, ssq, o);
        sm  += __shfl_xor_sync(0xffffffffu, sm , o);
    }
    float inv_norm = 1.f / fmaxf(sqrtf(ssq), 1e-12f);
#pragma unroll
    for (int c = 0; c < 2; c++) {
        int d0 = (c * 32 + lane) * 4;
        __nv_bfloat162 p0 = __floats2bfloat162_rn(v[c*4+0]*inv_norm, v[c*4+1]*inv_norm);
        __nv_bfloat162 p1 = __floats2bfloat162_rn(v[c*4+2]*inv_norm, v[c*4+3]*inv_norm);
        uint2 pk; pk.x = *(uint32_t*)&p0; pk.y = *(uint32_t*)&p1;
        *(uint2*)&g_fbf[(size_t)row * ND + d0] = pk;
    }
    if (lane == 0) {
        g_dsq[row] = dsq;
        g_accL0[row] = 0.f;
        g_accT[row]  = 0.f;
        int isn = (lab[row] == 0);
        sh_sm[wrp]  = isn ? (double)sm  : 0.0;
        sh_ssq[wrp] = isn ? (double)ssq : 0.0;
        sh_ctr[wrp] = isn ? (double)dsq : 0.0;
        sh_cnt[wrp] = isn;
    }
    __syncthreads();
    if (threadIdx.x == 0) {
        double a = 0, b2 = 0, c2 = 0; int n = 0;
#pragma unroll
        for (int w = 0; w < 8; w++) { a += sh_sm[w]; b2 += sh_ssq[w]; c2 += sh_ctr[w]; n += sh_cnt[w]; }
        p_sum[blockIdx.x] = a; p_ssq[blockIdx.x] = b2;
        p_ctr[blockIdx.x] = c2; p_cnt[blockIdx.x] = n;
    }
}

// ---------------- pass 2: reduce partials, sigma/margin scalar ----------------
__global__ void sigma_k(const float* __restrict__ rsig) {
    __shared__ double r0[256], r1[256], r2[256];
    __shared__ int    r3[256];
    int t = threadIdx.x;
    double a = 0, b = 0, c = 0; int n = 0;
#pragma unroll
    for (int q = 0; q < RSB / 256; q++) {
        int idx = t + q * 256;
        a += p_sum[idx]; b += p_ssq[idx]; c += p_ctr[idx]; n += p_cnt[idx];
    }
    r0[t] = a; r1[t] = b; r2[t] = c; r3[t] = n;
    __syncthreads();
    for (int o = 128; o > 0; o >>= 1) {
        if (t < o) { r0[t] += r0[t+o]; r1[t] += r1[t+o]; r2[t] += r2[t+o]; r3[t] += r3[t+o]; }
        __syncthreads();
    }
    if (t == 0) {
        int cnt = r3[0];
        double n_el  = (double)cnt * (double)ND;
        double var   = (r1[0] - r0[0] * r0[0] / n_el) / (n_el - 1.0);
        double sigma = 0.9 * (double)rsig[0] + 0.1 * sqrt(var);
        g_m = (float)(0.5 + 0.3 * sigma + 0.3 * (1.0 - 224.0 / 900.0));
        g_center_d = r2[0];
        g_cnt = cnt;
        g_mc_d = 0.0;
        g_ticket = 0u;
    }
}

// ---------------- pass 3: triangle-tiled bf16 mma contrastive ----------------
// 3-stage cp.async pipeline, one __syncthreads per k-block.
__global__ void __launch_bounds__(256, 2) contrast_mma(const int* __restrict__ lab) {
    extern __shared__ __align__(16) char dsm[];
    __shared__ float s_w0c[BN];
    __shared__ float s_w0r[BM];

    // invert linear triangle index -> (ti, tj), tj >= ti
    int b = blockIdx.x;
    int ti = (int)((129.0 - sqrt(129.0 * 129.0 - 8.0 * (double)b)) * 0.5);
    int base = ti * NTILE - (ti * (ti - 1)) / 2;
    if (b < base) { ti--; base = ti * NTILE - (ti * (ti - 1)) / 2; }
    else if (b >= base + (NTILE - ti)) { ti++; base = ti * NTILE - (ti * (ti - 1)) / 2; }
    const int tj = ti + (b - base);

    const uint32_t sbase = smem_u32(dsm);
    const int tid = threadIdx.x, lane = tid & 31, wid = tid >> 5;
    const int wm = wid & 3, wn = wid >> 2;
    const int i0 = ti * BM, j0 = tj * BN;
    const bool diag = (ti == tj);

    for (int j = tid; j < BN; j += 256)
        s_w0c[j] = (lab[j0 + j] == 0) ? 1.f : 0.f;
    for (int i = tid; i < BM; i += 256)
        s_w0r[i] = (lab[i0 + i] == 0) ? 1.f : 0.f;

    float c[2][8][4];
#pragma unroll
    for (int fm = 0; fm < 2; fm++)
#pragma unroll
        for (int fn = 0; fn < 8; fn++)
#pragma unroll
            for (int e = 0; e < 4; e++) c[fm][fn][e] = 0.f;

    auto prefetch = [&](int kb) {
        uint32_t a_s = sbase + (uint32_t)(kb % 3) * 32768u;
        uint32_t b_s = a_s + 16384u;
        const __nv_bfloat16* gA = g_fbf + (size_t)i0 * ND + kb * BK;
        const __nv_bfloat16* gB = g_fbf + (size_t)j0 * ND + kb * BK;
#pragma unroll
        for (int it = 0; it < 4; it++) {
            int ch = tid + it * 256;
            int row = ch >> 3, c16 = ch & 7;
            uint32_t sw = (uint32_t)(row * 128 + ((c16 ^ (row & 7)) << 4));
            cp_async16(a_s + sw, gA + (size_t)row * ND + c16 * 8);
            cp_async16(b_s + sw, gB + (size_t)row * ND + c16 * 8);
        }
        asm volatile("cp.async.commit_group;" ::: "memory");
    };

    prefetch(0);
    prefetch(1);

#pragma unroll 1
    for (int kb = 0; kb < ND / BK; kb++) {
        if (kb < ND / BK - 1)
            asm volatile("cp.async.wait_group 1;" ::: "memory");
        else
            asm volatile("cp.async.wait_group 0;" ::: "memory");
        __syncthreads();
        if (kb + 2 < ND / BK) prefetch(kb + 2);

        uint32_t a_s = sbase + (uint32_t)(kb % 3) * 32768u;
        uint32_t b_s = a_s + 16384u;

#pragma unroll
        for (int ks = 0; ks < 4; ks++) {
            uint32_t a_frag[2][4], b_frag[4][4];
            int c16 = ks * 2 + (lane >> 4);
#pragma unroll
            for (int fm = 0; fm < 2; fm++) {
                int row = wm * 32 + fm * 16 + (lane & 15);
                ldsm_x4(a_frag[fm], a_s + row * 128 + ((c16 ^ (row & 7)) << 4));
            }
#pragma unroll
            for (int g = 0; g < 4; g++) {
                int row = wn * 64 + g * 16 + (lane & 15);
                ldsm_x4(b_frag[g], b_s + row * 128 + ((c16 ^ (row & 7)) << 4));
            }
#pragma unroll
            for (int fm = 0; fm < 2; fm++)
#pragma unroll
                for (int fn = 0; fn < 8; fn++) {
                    int g = fn >> 1;
                    uint32_t b0 = (fn & 1) ? b_frag[g][1] : b_frag[g][0];
                    uint32_t b1 = (fn & 1) ? b_frag[g][3] : b_frag[g][2];
                    mma16816(c[fm][fn], a_frag[fm], b0, b1);
                }
        }
    }

    // ---- epilogue (register-lean; fn outer, col partials short-lived) ----
    const int rl = wm * 32 + (lane >> 2);
    const int r_base = i0 + rl;
    float racc[8];
#pragma unroll
    for (int q = 0; q < 8; q++) racc[q] = 0.f;

    if (!diag) {
        float wr0 = s_w0r[rl], wr1 = s_w0r[rl + 8];
        float wr2 = s_w0r[rl + 16], wr3 = s_w0r[rl + 24];
#pragma unroll
        for (int fn = 0; fn < 8; fn++) {
            int jl = wn * 64 + fn * 8 + (lane & 3) * 2;
            float w0a = s_w0c[jl], w0b = s_w0c[jl + 1];
            float cTa = 0.f, cTb = 0.f, c0a = 0.f, c0b = 0.f;
#pragma unroll
            for (int fm = 0; fm < 2; fm++) {
                float e00 = ex2f(c[fm][fn][0] * CEXP);
                float e01 = ex2f(c[fm][fn][1] * CEXP);
                float e10 = ex2f(c[fm][fn][2] * CEXP);
                float e11 = ex2f(c[fm][fn][3] * CEXP);
                racc[fm*4+0] = fmaf(e00, w0a, fmaf(e01, w0b, racc[fm*4+0]));
                racc[fm*4+1] += e00 + e01;
                racc[fm*4+2] = fmaf(e10, w0a, fmaf(e11, w0b, racc[fm*4+2]));
                racc[fm*4+3] += e10 + e11;
                float wrA = fm ? wr2 : wr0, wrB = fm ? wr3 : wr1;
                cTa += e00 + e10; cTb += e01 + e11;
                c0a = fmaf(e00, wrA, fmaf(e10, wrB, c0a));
                c0b = fmaf(e01, wrA, fmaf(e11, wrB, c0b));
            }
#pragma unroll
            for (int o = 4; o <= 16; o <<= 1) {
                cTa += __shfl_xor_sync(0xffffffffu, cTa, o);
                cTb += __shfl_xor_sync(0xffffffffu, cTb, o);
                c0a += __shfl_xor_sync(0xffffffffu, c0a, o);
                c0b += __shfl_xor_sync(0xffffffffu, c0b, o);
            }
            if ((lane >> 2) == 0) {
                int jc = j0 + wn * 64 + fn * 8 + lane * 2;
                atomicAdd(&g_accT[jc],      cTa);
                atomicAdd(&g_accT[jc + 1],  cTb);
                atomicAdd(&g_accL0[jc],     c0a);
                atomicAdd(&g_accL0[jc + 1], c0b);
            }
        }
    } else {
#pragma unroll
        for (int fn = 0; fn < 8; fn++) {
            int jl = wn * 64 + fn * 8 + (lane & 3) * 2;
            int jg = j0 + jl;
            float w0a = s_w0c[jl], w0b = s_w0c[jl + 1];
#pragma unroll
            for (int fm = 0; fm < 2; fm++) {
                int r0 = r_base + fm * 16, r1 = r0 + 8;
                float e00 = ex2f(c[fm][fn][0] * CEXP);
                float e01 = ex2f(c[fm][fn][1] * CEXP);
                float e10 = ex2f(c[fm][fn][2] * CEXP);
                float e11 = ex2f(c[fm][fn][3] * CEXP);
                if (r0 == jg)     e00 = 0.f;
                if (r0 == jg + 1) e01 = 0.f;
                if (r1 == jg)     e10 = 0.f;
                if (r1 == jg + 1) e11 = 0.f;
                racc[fm*4+0] = fmaf(e00, w0a, fmaf(e01, w0b, racc[fm*4+0]));
                racc[fm*4+1] += e00 + e01;
                racc[fm*4+2] = fmaf(e10, w0a, fmaf(e11, w0b, racc[fm*4+2]));
                racc[fm*4+3] += e10 + e11;
            }
        }
    }

#pragma unroll
    for (int o = 1; o < 4; o <<= 1)
#pragma unroll
        for (int q = 0; q < 8; q++)
            racc[q] += __shfl_xor_sync(0xffffffffu, racc[q], o);

    if ((lane & 3) == 0) {
#pragma unroll
        for (int fm = 0; fm < 2; fm++) {
            int r0 = r_base + fm * 16, r1 = r0 + 8;
            atomicAdd(&g_accL0[r0], racc[fm*4+0]);
            atomicAdd(&g_accT[r0],  racc[fm*4+1]);
            atomicAdd(&g_accL0[r1], racc[fm*4+2]);
            atomicAdd(&g_accT[r1],  racc[fm*4+3]);
        }
    }
}

// ---------------- pass 4: per-row margin + contrastive + final write -------
__global__ void con_final(const int* __restrict__ lab, float* __restrict__ out) {
    int i = blockIdx.x * 256 + threadIdx.x;
    int lane = threadIdx.x & 31;
    int n0 = g_cnt, n1 = NB - n0;
    float m = g_m;

    int li = lab[i];
    float aT = g_accT[i], a0 = g_accL0[i];
    float pos = (li == 0) ? a0 : (aT - a0);
    int npos = ((li == 0) ? n0 : n1) - 1;
    int nneg = (li == 0) ? n1 : n0;
    float loc = 0.f;
    if (npos > 0 && nneg > 0)
        loc = 0.5f * (logf(aT + 1e-8f) - logf(pos));        // GAMMA*r_con
    if (li == 1)
        loc += fmaxf(m - sqrtf(g_dsq[i]), 0.f);             // BETA*r_margin
    double d = (double)loc;
#pragma unroll
    for (int o = 16; o > 0; o >>= 1)
        d += __shfl_xor_sync(0xffffffffu, d, o);
    if (lane == 0) {
        atomicAdd(&g_mc_d, d);
        __threadfence();
        unsigned t = atomicAdd(&g_ticket, 1u);
        if (t == (NB / 32) - 1)                             // last warp: finalize
            out[0] = (float)((g_center_d + g_mc_d) / (double)NB);
    }
}

// ---------------- launch ----------------
extern "C" void kernel_launch(void* const* d_in, const int* in_sizes, int n_in,
                              void* d_out, int out_size) {
    const float* feat = (const float*)d_in[0];
    const int*   lab  = (const int*)d_in[1];
    const float* cen  = (const float*)d_in[2];
    const float* rsig = (const float*)d_in[3];
    float* out = (float*)d_out;

    cudaFuncSetAttribute(contrast_mma,
                         cudaFuncAttributeMaxDynamicSharedMemorySize, 98304);

    row_stats<<<RSB, 256>>>(feat, lab, cen);
    sigma_k<<<1, 256>>>(rsig);
    contrast_mma<<<NBLK, 256, 98304>>>(lab);
    con_final<<<NB / 256, 256>>>(lab, out);
}